// round 14
// baseline (speedup 1.0000x reference)
#include <cuda_runtime.h>
#include <cuda_fp16.h>
#include <cstdint>

#define BB 64
#define NN 147
#define NSQ (NN*NN)          // 21609

// ---------------- scratch (device globals; zero-initialized) -----------------
__device__ float g_ahat[(size_t)BB * NSQ];      // A_hat (unnormalized) [b][t][s]
__device__ float g_dinv[BB * NN];
__device__ uint32_t g_x0h[(size_t)BB * NN * 16];     // node feats fp16 [node][16 words]
__device__ uint32_t g_xwTA[(size_t)BB * 128 * 80];   // XW^T fp16 [b][f][160 s] ping
__device__ uint32_t g_xwTB[(size_t)BB * 128 * 80];   // pong (pads stay zero)
__device__ float g_fa[(size_t)BB * NN * 128];   // final GCN output (fp32)

__device__ uint32_t g_w2h[9*32*8];   // conv2 w fp16, k-pair interleaved
__device__ uint32_t g_w1t[32*16];    // conv1 w tf32: [k][o], k>=27 -> 0
__device__ uint32_t g_wg1[64*16];    // gcn1_w fp16 T: [n][q=k/2], K=32
__device__ uint32_t g_wg2[128*32];   // gcn2_w fp16 T: [n][q], K=64
__device__ uint32_t g_wg3[128*64];   // gcn3_w fp16 T: [n][q], K=128

__device__ __forceinline__ uint32_t f2tf32(float f) {
    uint32_t r;
    asm("cvt.rna.tf32.f32 %0, %1;" : "=r"(r) : "f"(f));
    return r;
}
__device__ __forceinline__ uint32_t packh2(float lo, float hi) {
    __half2 h = __floats2half2_rn(lo, hi);
    return *(uint32_t*)&h;
}

#define MMA_TF32(d, a0_, a1_, a2_, a3_, b0_, b1_)                              \
    asm volatile("mma.sync.aligned.m16n8k8.row.col.f32.tf32.tf32.f32 "         \
                 "{%0,%1,%2,%3}, {%4,%5,%6,%7}, {%8,%9}, {%0,%1,%2,%3};"       \
                 : "+f"((d)[0]), "+f"((d)[1]), "+f"((d)[2]), "+f"((d)[3])      \
                 : "r"(a0_), "r"(a1_), "r"(a2_), "r"(a3_), "r"(b0_), "r"(b1_))

#define MMA_F16(d, a0_, a1_, a2_, a3_, b0_, b1_)                               \
    asm volatile("mma.sync.aligned.m16n8k16.row.col.f32.f16.f16.f32 "          \
                 "{%0,%1,%2,%3}, {%4,%5,%6,%7}, {%8,%9}, {%0,%1,%2,%3};"       \
                 : "+f"((d)[0]), "+f"((d)[1]), "+f"((d)[2]), "+f"((d)[3])      \
                 : "r"(a0_), "r"(a1_), "r"(a2_), "r"(a3_), "r"(b0_), "r"(b1_))

// ---------------- one-time weight relayout/convert (single kernel) -----------
__global__ void prep_kernel(const float* __restrict__ w1,
                            const float* __restrict__ w2,
                            const float* __restrict__ wg1,
                            const float* __restrict__ wg2,
                            const float* __restrict__ wg3) {
    int i = blockIdx.x * 256 + threadIdx.x;
    if (i < 2304) {                      // conv2 -> fp16, k-pair interleaved
        int row = i >> 3, j = i & 7;
        int tap = row >> 5, o = row & 31;
        int ci0 = 2*(j >> 1) + (j & 1)*8;
        g_w2h[i] = packh2(w2[(o*16 + ci0)*9 + tap], w2[(o*16 + ci0 + 1)*9 + tap]);
    }
    if (i < 512) {                       // conv1 -> tf32, k>=27 zero
        int k = i >> 4, o = i & 15;
        uint32_t v = 0u;
        if (k < 27) {
            int tap = (k*11) >> 5, c = k - 3*tap;
            int kh = (tap*11) >> 5, kw = tap - 3*kh;
            v = f2tf32(w1[((o*3 + c)*3 + kh)*3 + kw]);   // OIHW
        }
        g_w1t[i] = v;
    }
    if (i < 1024) {
        int n = i >> 4, q = i & 15;
        g_wg1[i] = packh2(wg1[2*q*64 + n], wg1[(2*q + 1)*64 + n]);
    }
    if (i < 4096) {
        int n = i >> 5, q = i & 31;
        g_wg2[i] = packh2(wg2[2*q*128 + n], wg2[(2*q + 1)*128 + n]);
    }
    if (i < 8192) {
        int n = i >> 6, q = i & 63;
        g_wg3[i] = packh2(wg3[2*q*128 + n], wg3[(2*q + 1)*128 + n]);
    }
}

// ====== fused conv1(3->16, tf32 MMA) + conv2(16->32, fp16 MMA) + epilogue ====
// grid: (5, 19, B). block = 256 threads = 8x32 output tile (warp = 1 img row).
#define PST 8                             // patch pixel stride (words), k-interleaved
#define PPX 340                           // patch pixels: 10 rows x 34 cols
__global__ void __launch_bounds__(256)
conv_fused_kernel(const float* __restrict__ obs,
                  const float* __restrict__ b1,
                  const float* __restrict__ b2) {
    __shared__ uint32_t sW2h[9*32*8];     // 9.2 KB
    __shared__ uint32_t sPu[PPX*PST];     // 10.9 KB fp16 h1 patch (k-interleaved)
    __shared__ uint32_t sObs32[1408];     // 12x36x3 tf32 + zero pad
    __shared__ uint32_t sW1u[512];
    __shared__ float sb1[16];

    int tid = threadIdx.x;
    int lane = tid & 31, warp = tid >> 5;
    int gid = lane >> 2, tig = lane & 3;
    int b   = blockIdx.z;
    int bw0 = blockIdx.x * 32;
    int bh0 = blockIdx.y * 8;

    {   // stage weights: coalesced copies
        uint4* dst = (uint4*)sW2h;
        const uint4* src = (const uint4*)g_w2h;
        for (int i = tid; i < 576; i += 256) dst[i] = src[i];
        if (tid < 128) ((uint4*)sW1u)[tid] = ((const uint4*)g_w1t)[tid];
    }
    if (tid < 16) sb1[tid] = b1[tid];
    if (tid >= 144 && tid < 256) sObs32[1296 + tid - 144] = 0u;   // pad finite

    // obs halo patch (tf32): rows bh0-2..bh0+9, cols bw0-2..bw0+33
    for (int i = tid; i < 1296; i += 256) {
        int pr = i / 108, within = i - pr*108;
        int hi = bh0 + pr - 2;
        int wi = bw0 - 2 + within/3;
        float v = 0.0f;
        if (hi >= 0 && hi < NN && wi >= 0 && wi < NN)
            v = obs[(size_t)(b*NN + hi)*NN*3 + (bw0 - 2)*3 + within];
        sObs32[i] = f2tf32(v);
    }
    __syncthreads();

    // ---------- conv1 via tf32 MMA: A = 384 px x K32 im2col, B = w1 ---------
    {
        int offA[4][2];
#pragma unroll
        for (int ks = 0; ks < 4; ks++) {
#pragma unroll
            for (int hh = 0; hh < 2; hh++) {
                int k = ks*8 + tig + hh*4;
                int tap = (k*11) >> 5, c = k - 3*tap;
                int kh = (tap*11) >> 5, kw = tap - 3*kh;
                offA[ks][hh] = kh*108 + kw*3 + c;
            }
        }

        float accP[3][2][4];
#pragma unroll
        for (int mt = 0; mt < 3; mt++)
#pragma unroll
            for (int nt = 0; nt < 2; nt++)
#pragma unroll
                for (int q = 0; q < 4; q++) accP[mt][nt][q] = 0.0f;

#pragma unroll
        for (int mt = 0; mt < 3; mt++) {
            int p1 = warp*48 + mt*16 + gid;
            int p2 = p1 + 8;
            int p1c = min(p1, PPX-1), p2c = min(p2, PPX-1);
            int pr1 = p1c / 34, pr2 = p2c / 34;
            int bp1 = pr1*108 + (p1c - pr1*34)*3;
            int bp2 = pr2*108 + (p2c - pr2*34)*3;
#pragma unroll
            for (int ks = 0; ks < 4; ks++) {
                uint32_t a0 = sObs32[bp1 + offA[ks][0]];
                uint32_t a1 = sObs32[bp2 + offA[ks][0]];
                uint32_t a2 = sObs32[bp1 + offA[ks][1]];
                uint32_t a3 = sObs32[bp2 + offA[ks][1]];
#pragma unroll
                for (int nt = 0; nt < 2; nt++) {
                    int n = nt*8 + gid;
                    uint32_t b0 = sW1u[(ks*8 + tig)*16 + n];
                    uint32_t b1v = sW1u[(ks*8 + tig + 4)*16 + n];
                    MMA_TF32(accP[mt][nt], a0, a1, a2, a3, b0, b1v);
                }
            }
        }

        // bias+relu, zero invalid pixels, STS.64 k-pair interleaved
#pragma unroll
        for (int mt = 0; mt < 3; mt++) {
#pragma unroll
            for (int hp = 0; hp < 2; hp++) {
                int p = warp*48 + mt*16 + gid + hp*8;
                if (p < PPX) {
                    int pr = p / 34, pc = p - pr*34;
                    int hi = bh0 + pr - 1, wi = bw0 + pc - 1;
                    bool valid = (hi >= 0 && hi < NN && wi >= 0 && wi < NN);
                    uint32_t wlo = 0u, whi = 0u;
                    if (valid) {
                        int ch0 = 2*tig;           // nt = 0
                        int ch1 = 8 + 2*tig;       // nt = 1
                        wlo = packh2(fmaxf(accP[mt][0][hp*2]   + sb1[ch0],   0.0f),
                                     fmaxf(accP[mt][0][hp*2+1] + sb1[ch0+1], 0.0f));
                        whi = packh2(fmaxf(accP[mt][1][hp*2]   + sb1[ch1],   0.0f),
                                     fmaxf(accP[mt][1][hp*2+1] + sb1[ch1+1], 0.0f));
                    }
                    ((uint2*)sPu)[p*4 + tig] = make_uint2(wlo, whi);
                }
            }
        }
    }
    __syncthreads();

    // ---------- conv2 via fp16 MMA: one k16 chunk per tap, LDS.64 frags ------
    float acc[2][4][4];
#pragma unroll
    for (int mt = 0; mt < 2; mt++)
#pragma unroll
        for (int nt = 0; nt < 4; nt++)
#pragma unroll
            for (int q = 0; q < 4; q++) acc[mt][nt][q] = 0.0f;

    const uint2* sPu2 = (const uint2*)sPu;
    const uint2* sW2  = (const uint2*)sW2h;

#pragma unroll
    for (int th = 0; th < 3; th++) {
#pragma unroll
        for (int tw = 0; tw < 3; tw++) {
            int tap = th*3 + tw;
            uint2 bf[4];
#pragma unroll
            for (int nt = 0; nt < 4; nt++)
                bf[nt] = sW2[(tap*32 + nt*8 + gid)*4 + tig];
#pragma unroll
            for (int mt = 0; mt < 2; mt++) {
                int P1 = (warp + th)*34 + mt*16 + gid + tw;
                uint2 A0 = sPu2[P1*4 + tig];
                uint2 A1 = sPu2[(P1+8)*4 + tig];
#pragma unroll
                for (int nt = 0; nt < 4; nt++)
                    MMA_F16(acc[mt][nt], A0.x, A1.x, A0.y, A1.y,
                            bf[nt].x, bf[nt].y);
            }
        }
    }

    // ---------- register epilogue: quad-shuffle channel mean -----------------
    {
        float bv[4][2];
#pragma unroll
        for (int nt = 0; nt < 4; nt++) {
            bv[nt][0] = __ldg(b2 + nt*8 + 2*tig);
            bv[nt][1] = __ldg(b2 + nt*8 + 2*tig + 1);
        }
        int h = bh0 + warp;
#pragma unroll
        for (int mt = 0; mt < 2; mt++) {
#pragma unroll
            for (int rh = 0; rh < 2; rh++) {
                float y[8];
                float s = 0.0f;
#pragma unroll
                for (int nt = 0; nt < 4; nt++) {
                    float u0 = fmaxf(acc[mt][nt][rh*2]   + bv[nt][0], 0.0f);
                    float u1 = fmaxf(acc[mt][nt][rh*2+1] + bv[nt][1], 0.0f);
                    y[nt*2] = u0; y[nt*2+1] = u1;
                    s += u0 + u1;
                }
                s += __shfl_xor_sync(0xffffffff, s, 1);
                s += __shfl_xor_sync(0xffffffff, s, 2);
                int wq = bw0 + mt*16 + gid + rh*8;
                if (h < NN && wq < NN) {
                    if (tig == 0)
                        g_ahat[(size_t)b*NSQ + (size_t)wq*NN + h] =
                            s * (1.0f/32.0f) + (h == wq ? 1.0f : 0.0f);
                    if (h == wq) {
                        uint32_t* xp = g_x0h + ((size_t)b*NN + h)*16;
#pragma unroll
                        for (int nt = 0; nt < 4; nt++)
                            xp[nt*4 + tig] = packh2(y[nt*2], y[nt*2+1]);
                    }
                }
            }
        }
    }
}

// ------ merged: deg (blocks >= 147) + XW1^T fp16 MMA (blocks 0..146) ---------
__global__ void xwdeg_kernel() {
    if (blockIdx.x >= 147) {
        int bt = blockIdx.x - 147;
        const float* row = g_ahat + (size_t)bt * NN;
        int tid = threadIdx.x;
        float s = 0.0f;
        for (int i = tid; i < NN; i += 128) s += row[i];
#pragma unroll
        for (int o = 16; o > 0; o >>= 1) s += __shfl_xor_sync(0xffffffff, s, o);
        __shared__ float ws[4];
        if ((tid & 31) == 0) ws[tid >> 5] = s;
        __syncthreads();
        if (tid == 0) {
            float d = ws[0] + ws[1] + ws[2] + ws[3];
            g_dinv[bt] = d > 0.0f ? rsqrtf(d) : 0.0f;
        }
        return;
    }

    int lane = threadIdx.x & 31, warp = threadIdx.x >> 5;
    int gid = lane >> 2, tig = lane & 3;
    int m0 = blockIdx.x * 64 + warp * 16;

    float acc[8][4];
#pragma unroll
    for (int nt = 0; nt < 8; nt++)
#pragma unroll
        for (int q = 0; q < 4; q++) acc[nt][q] = 0.0f;

    int r0 = m0 + gid, r1 = r0 + 8;
#pragma unroll
    for (int ks = 0; ks < 2; ks++) {
        uint32_t a0 = g_x0h[(size_t)r0*16 + ks*8 + tig];
        uint32_t a1 = g_x0h[(size_t)r1*16 + ks*8 + tig];
        uint32_t a2 = g_x0h[(size_t)r0*16 + ks*8 + tig + 4];
        uint32_t a3 = g_x0h[(size_t)r1*16 + ks*8 + tig + 4];
#pragma unroll
        for (int nt = 0; nt < 8; nt++) {
            int n = nt*8 + gid;
            uint32_t b0 = g_wg1[n*16 + ks*8 + tig];
            uint32_t b1 = g_wg1[n*16 + ks*8 + tig + 4];
            MMA_F16(acc[nt], a0, a1, a2, a3, b0, b1);
        }
    }

    __half* dst = (__half*)g_xwTA;
    int b0i = r0 / NN, s0 = r0 - b0i*NN;
    int b1i = r1 / NN, s1 = r1 - b1i*NN;
#pragma unroll
    for (int nt = 0; nt < 8; nt++) {
        int col = nt*8 + 2*tig;
        dst[((size_t)b0i*128 + col    )*160 + s0] = __float2half(acc[nt][0]);
        dst[((size_t)b0i*128 + col + 1)*160 + s0] = __float2half(acc[nt][1]);
        dst[((size_t)b1i*128 + col    )*160 + s1] = __float2half(acc[nt][2]);
        dst[((size_t)b1i*128 + col + 1)*160 + s1] = __float2half(acc[nt][3]);
    }
}

// --- GCN layer: Y = relu(norm @ XW_in^T' + b); then XW_out^T = (Y @ Wn)^T ----
// B operands of the agg GEMM are PREFETCHED into registers before smem staging
// so the ~250cyc L2 latency overlaps the A-tile build (fixes regs=32/issue=20%).
template<int FOUT, bool LAST>
__global__ void __launch_bounds__(128)
gcn_kernel(const uint32_t* __restrict__ XWT_in,
           const float* __restrict__ bias,
           const uint32_t* __restrict__ Wn,
           uint32_t* __restrict__ XWT_out,
           float* __restrict__ Yout) {
    constexpr int NTW  = FOUT / 32;
    constexpr int SYW  = FOUT/2 + 4;
    __shared__ uint32_t sA[16 * 84];
    __shared__ float sds[160];
    __shared__ uint32_t sY[16 * SYW];

    int tid = threadIdx.x;
    int lane = tid & 31, warp = tid >> 5;
    int gid = lane >> 2, tig = lane & 3;
    int b = blockIdx.y, t0 = blockIdx.x * 16;

    // ---- prefetch ALL agg-GEMM B fragments (block-unique gmem traffic) ----
    uint32_t breg[10][NTW][2];
    {
        int wn0 = warp * (FOUT/4);
        const uint32_t* xwb = XWT_in + (size_t)b * 128 * 80;
#pragma unroll
        for (int ks = 0; ks < 10; ks++)
#pragma unroll
            for (int nt = 0; nt < NTW; nt++) {
                int n = wn0 + nt*8 + gid;
                breg[ks][nt][0] = __ldg(xwb + (size_t)n*80 + ks*8 + tig);
                breg[ks][nt][1] = __ldg(xwb + (size_t)n*80 + ks*8 + tig + 4);
            }
    }

    for (int i = tid; i < 160; i += 128)
        sds[i] = (i < NN) ? g_dinv[b*NN + i] : 0.0f;
    __syncthreads();

    {
        __half* sAh = (__half*)sA;
        const float* ab = g_ahat + (size_t)b * NSQ;
        for (int i = tid; i < 16*168; i += 128) {
            int r = i / 168, s = i - r*168;
            int t = t0 + r;
            float v = 0.0f;
            if (t < NN && s < NN) v = ab[(size_t)t*NN + s] * sds[t] * sds[s];
            sAh[r*168 + s] = __float2half(v);
        }
    }
    __syncthreads();

    float acc[NTW][4];
#pragma unroll
    for (int nt = 0; nt < NTW; nt++)
#pragma unroll
        for (int q = 0; q < 4; q++) acc[nt][q] = 0.0f;

    int wn0 = warp * (FOUT/4);

#pragma unroll
    for (int ks = 0; ks < 10; ks++) {
        uint32_t a0 = sA[gid*84 + ks*8 + tig];
        uint32_t a1 = sA[(gid+8)*84 + ks*8 + tig];
        uint32_t a2 = sA[gid*84 + ks*8 + tig + 4];
        uint32_t a3 = sA[(gid+8)*84 + ks*8 + tig + 4];
#pragma unroll
        for (int nt = 0; nt < NTW; nt++)
            MMA_F16(acc[nt], a0, a1, a2, a3, breg[ks][nt][0], breg[ks][nt][1]);
    }

    int r0 = t0 + gid, r1 = r0 + 8;
#pragma unroll
    for (int nt = 0; nt < NTW; nt++) {
        int col = wn0 + nt*8 + 2*tig;
        float bv0 = __ldg(bias + col), bv1 = __ldg(bias + col + 1);
        float y00 = fmaxf(acc[nt][0] + bv0, 0.0f);
        float y01 = fmaxf(acc[nt][1] + bv1, 0.0f);
        float y10 = fmaxf(acc[nt][2] + bv0, 0.0f);
        float y11 = fmaxf(acc[nt][3] + bv1, 0.0f);
        if (LAST) {
            if (r0 < NN)
                *(float2*)&Yout[(size_t)(b*NN + r0)*FOUT + col] = make_float2(y00, y01);
            if (r1 < NN)
                *(float2*)&Yout[(size_t)(b*NN + r1)*FOUT + col] = make_float2(y10, y11);
        } else {
            int wq = wn0/2 + nt*4 + tig;
            sY[gid*SYW + wq]     = packh2(y00, y01);
            sY[(gid+8)*SYW + wq] = packh2(y10, y11);
        }
    }

    if (!LAST) {
        __syncthreads();

        float acc2[4][4];
#pragma unroll
        for (int nt = 0; nt < 4; nt++)
#pragma unroll
            for (int q = 0; q < 4; q++) acc2[nt][q] = 0.0f;

        int wn2 = warp * 32;
#pragma unroll
        for (int ks = 0; ks < FOUT/16; ks++) {
            uint32_t a0 = sY[gid*SYW + ks*8 + tig];
            uint32_t a1 = sY[(gid+8)*SYW + ks*8 + tig];
            uint32_t a2 = sY[gid*SYW + ks*8 + tig + 4];
            uint32_t a3 = sY[(gid+8)*SYW + ks*8 + tig + 4];
#pragma unroll
            for (int nt = 0; nt < 4; nt++) {
                int n = wn2 + nt*8 + gid;
                uint32_t b0 = __ldg(Wn + n*(FOUT/2) + ks*8 + tig);
                uint32_t b1 = __ldg(Wn + n*(FOUT/2) + ks*8 + tig + 4);
                MMA_F16(acc2[nt], a0, a1, a2, a3, b0, b1);
            }
        }

        __half* dst = (__half*)XWT_out;
#pragma unroll
        for (int nt = 0; nt < 4; nt++) {
            int col = wn2 + nt*8 + 2*tig;
            if (r0 < NN) {
                dst[((size_t)b*128 + col    )*160 + r0] = __float2half(acc2[nt][0]);
                dst[((size_t)b*128 + col + 1)*160 + r0] = __float2half(acc2[nt][1]);
            }
            if (r1 < NN) {
                dst[((size_t)b*128 + col    )*160 + r1] = __float2half(acc2[nt][2]);
                dst[((size_t)b*128 + col + 1)*160 + r1] = __float2half(acc2[nt][3]);
            }
        }
    }
}

// ---------------- mean pool + policy head ------------------------------------
__global__ void head_kernel(const float* __restrict__ Y,
                            const float* __restrict__ pw,
                            const float* __restrict__ pb,
                            float* __restrict__ out) {
    int b = blockIdx.x;
    __shared__ float sp[128];
    int f = threadIdx.x;
    float s = 0.0f;
    const float* yb = Y + (size_t)b*NN*128;
    for (int n = 0; n < NN; n++) s += yb[n*128 + f];
    sp[f] = s * (1.0f / NN);
    __syncthreads();
    if (f < 5) {
        float a = pb[f];
#pragma unroll
        for (int i = 0; i < 128; i++) a += sp[i] * pw[i*5 + f];
        out[b*5 + f] = a;
    }
}

// ---------------- launch -----------------------------------------------------
extern "C" void kernel_launch(void* const* d_in, const int* in_sizes, int n_in,
                              void* d_out, int out_size) {
    const float* obs      = (const float*)d_in[0];
    const float* conv1_w  = (const float*)d_in[1];
    const float* conv1_b  = (const float*)d_in[2];
    const float* conv2_w  = (const float*)d_in[3];
    const float* conv2_b  = (const float*)d_in[4];
    const float* gcn1_w   = (const float*)d_in[5];
    const float* gcn1_b   = (const float*)d_in[6];
    const float* gcn2_w   = (const float*)d_in[7];
    const float* gcn2_b   = (const float*)d_in[8];
    const float* gcn3_w   = (const float*)d_in[9];
    const float* gcn3_b   = (const float*)d_in[10];
    const float* policy_w = (const float*)d_in[11];
    const float* policy_b = (const float*)d_in[12];
    float* out = (float*)d_out;

    float *fa;
    uint32_t *xwA, *xwB, *wg2, *wg3;
    cudaGetSymbolAddress((void**)&fa, g_fa);
    cudaGetSymbolAddress((void**)&xwA, g_xwTA);
    cudaGetSymbolAddress((void**)&xwB, g_xwTB);
    cudaGetSymbolAddress((void**)&wg2, g_wg2);
    cudaGetSymbolAddress((void**)&wg3, g_wg3);

    prep_kernel<<<32, 256>>>(conv1_w, conv2_w, gcn1_w, gcn2_w, gcn3_w);
    conv_fused_kernel<<<dim3(5, 19, BB), 256>>>(obs, conv1_b, conv2_b);
    xwdeg_kernel<<<147 + BB*NN, 128>>>();

    gcn_kernel<64,  false><<<dim3(10, BB), 128>>>(xwA, gcn1_b, wg2, xwB, nullptr);
    gcn_kernel<128, false><<<dim3(10, BB), 128>>>(xwB, gcn2_b, wg3, xwA, nullptr);
    gcn_kernel<128, true ><<<dim3(10, BB), 128>>>(xwA, gcn3_b, nullptr, nullptr, fa);

    head_kernel<<<BB, 128>>>(fa, policy_w, policy_b, out);
}

// round 15
// speedup vs baseline: 1.0695x; 1.0695x over previous
#include <cuda_runtime.h>
#include <cuda_fp16.h>
#include <cstdint>

#define BB 64
#define NN 147
#define NSQ (NN*NN)          // 21609

// ---------------- scratch (device globals; zero-initialized) -----------------
__device__ float g_ahat[(size_t)BB * NSQ];      // A_hat (unnormalized) [b][t][s]
__device__ float g_dinv[BB * NN];
__device__ uint32_t g_x0h[(size_t)BB * NN * 16];     // node feats fp16 [node][16 words]
__device__ uint32_t g_xwTA[(size_t)BB * 128 * 80];   // XW^T fp16 [b][f][160 s] ping
__device__ uint32_t g_xwTB[(size_t)BB * 128 * 80];   // pong (pads stay zero)
__device__ uint32_t g_normh[(size_t)BB * 10 * 1344]; // fp16 norm tiles [b][mt][16x84]
__device__ float g_pool[BB * 128];              // pooled sums (atomic)

__device__ uint32_t g_w2h[9*32*8];   // conv2 w fp16, k-pair interleaved
__device__ uint32_t g_w1t[32*16];    // conv1 w tf32: [k][o], k>=27 -> 0
__device__ uint32_t g_wg1[64*16];    // gcn1_w fp16 T: [n][q=k/2], K=32
__device__ uint32_t g_wg2[128*32];   // gcn2_w fp16 T: [n][q], K=64
__device__ uint32_t g_wg3[128*64];   // gcn3_w fp16 T: [n][q], K=128

__device__ __forceinline__ uint32_t f2tf32(float f) {
    uint32_t r;
    asm("cvt.rna.tf32.f32 %0, %1;" : "=r"(r) : "f"(f));
    return r;
}
__device__ __forceinline__ uint32_t packh2(float lo, float hi) {
    __half2 h = __floats2half2_rn(lo, hi);
    return *(uint32_t*)&h;
}

#define MMA_TF32(d, a0_, a1_, a2_, a3_, b0_, b1_)                              \
    asm volatile("mma.sync.aligned.m16n8k8.row.col.f32.tf32.tf32.f32 "         \
                 "{%0,%1,%2,%3}, {%4,%5,%6,%7}, {%8,%9}, {%0,%1,%2,%3};"       \
                 : "+f"((d)[0]), "+f"((d)[1]), "+f"((d)[2]), "+f"((d)[3])      \
                 : "r"(a0_), "r"(a1_), "r"(a2_), "r"(a3_), "r"(b0_), "r"(b1_))

#define MMA_F16(d, a0_, a1_, a2_, a3_, b0_, b1_)                               \
    asm volatile("mma.sync.aligned.m16n8k16.row.col.f32.f16.f16.f32 "          \
                 "{%0,%1,%2,%3}, {%4,%5,%6,%7}, {%8,%9}, {%0,%1,%2,%3};"       \
                 : "+f"((d)[0]), "+f"((d)[1]), "+f"((d)[2]), "+f"((d)[3])      \
                 : "r"(a0_), "r"(a1_), "r"(a2_), "r"(a3_), "r"(b0_), "r"(b1_))

// ---------------- one-time weight relayout/convert (single kernel) -----------
__global__ void prep_kernel(const float* __restrict__ w1,
                            const float* __restrict__ w2,
                            const float* __restrict__ wg1,
                            const float* __restrict__ wg2,
                            const float* __restrict__ wg3) {
    int i = blockIdx.x * 256 + threadIdx.x;
    g_pool[i] = 0.0f;                    // 32*256 == 8192 == BB*128 exactly
    if (i < 2304) {                      // conv2 -> fp16, k-pair interleaved
        int row = i >> 3, j = i & 7;
        int tap = row >> 5, o = row & 31;
        int ci0 = 2*(j >> 1) + (j & 1)*8;
        g_w2h[i] = packh2(w2[(o*16 + ci0)*9 + tap], w2[(o*16 + ci0 + 1)*9 + tap]);
    }
    if (i < 512) {                       // conv1 -> tf32, k>=27 zero
        int k = i >> 4, o = i & 15;
        uint32_t v = 0u;
        if (k < 27) {
            int tap = (k*11) >> 5, c = k - 3*tap;
            int kh = (tap*11) >> 5, kw = tap - 3*kh;
            v = f2tf32(w1[((o*3 + c)*3 + kh)*3 + kw]);   // OIHW
        }
        g_w1t[i] = v;
    }
    if (i < 1024) {
        int n = i >> 4, q = i & 15;
        g_wg1[i] = packh2(wg1[2*q*64 + n], wg1[(2*q + 1)*64 + n]);
    }
    if (i < 4096) {
        int n = i >> 5, q = i & 31;
        g_wg2[i] = packh2(wg2[2*q*128 + n], wg2[(2*q + 1)*128 + n]);
    }
    if (i < 8192) {
        int n = i >> 6, q = i & 63;
        g_wg3[i] = packh2(wg3[2*q*128 + n], wg3[(2*q + 1)*128 + n]);
    }
}

// ====== fused conv1(3->16, tf32 MMA) + conv2(16->32, fp16 MMA) + epilogue ====
// grid: (5, 19, B). block = 256 threads = 8x32 output tile (warp = 1 img row).
#define PST 8                             // patch pixel stride (words), k-interleaved
#define PPX 340                           // patch pixels: 10 rows x 34 cols
__global__ void __launch_bounds__(256)
conv_fused_kernel(const float* __restrict__ obs,
                  const float* __restrict__ b1,
                  const float* __restrict__ b2) {
    __shared__ uint32_t sW2h[9*32*8];     // 9.2 KB
    __shared__ uint32_t sPu[PPX*PST];     // 10.9 KB fp16 h1 patch (k-interleaved)
    __shared__ uint32_t sObs32[1408];     // 12x36x3 tf32 + zero pad
    __shared__ uint32_t sW1u[512];
    __shared__ float sb1[16];

    int tid = threadIdx.x;
    int lane = tid & 31, warp = tid >> 5;
    int gid = lane >> 2, tig = lane & 3;
    int b   = blockIdx.z;
    int bw0 = blockIdx.x * 32;
    int bh0 = blockIdx.y * 8;

    {   // stage weights: coalesced copies
        uint4* dst = (uint4*)sW2h;
        const uint4* src = (const uint4*)g_w2h;
        for (int i = tid; i < 576; i += 256) dst[i] = src[i];
        if (tid < 128) ((uint4*)sW1u)[tid] = ((const uint4*)g_w1t)[tid];
    }
    if (tid < 16) sb1[tid] = b1[tid];
    if (tid >= 144 && tid < 256) sObs32[1296 + tid - 144] = 0u;   // pad finite

    // obs halo patch (tf32): rows bh0-2..bh0+9, cols bw0-2..bw0+33
    for (int i = tid; i < 1296; i += 256) {
        int pr = i / 108, within = i - pr*108;
        int hi = bh0 + pr - 2;
        int wi = bw0 - 2 + within/3;
        float v = 0.0f;
        if (hi >= 0 && hi < NN && wi >= 0 && wi < NN)
            v = obs[(size_t)(b*NN + hi)*NN*3 + (bw0 - 2)*3 + within];
        sObs32[i] = f2tf32(v);
    }
    __syncthreads();

    // ---------- conv1 via tf32 MMA: A = 384 px x K32 im2col, B = w1 ---------
    {
        int offA[4][2];
#pragma unroll
        for (int ks = 0; ks < 4; ks++) {
#pragma unroll
            for (int hh = 0; hh < 2; hh++) {
                int k = ks*8 + tig + hh*4;
                int tap = (k*11) >> 5, c = k - 3*tap;
                int kh = (tap*11) >> 5, kw = tap - 3*kh;
                offA[ks][hh] = kh*108 + kw*3 + c;
            }
        }

        float accP[3][2][4];
#pragma unroll
        for (int mt = 0; mt < 3; mt++)
#pragma unroll
            for (int nt = 0; nt < 2; nt++)
#pragma unroll
                for (int q = 0; q < 4; q++) accP[mt][nt][q] = 0.0f;

#pragma unroll
        for (int mt = 0; mt < 3; mt++) {
            int p1 = warp*48 + mt*16 + gid;
            int p2 = p1 + 8;
            int p1c = min(p1, PPX-1), p2c = min(p2, PPX-1);
            int pr1 = p1c / 34, pr2 = p2c / 34;
            int bp1 = pr1*108 + (p1c - pr1*34)*3;
            int bp2 = pr2*108 + (p2c - pr2*34)*3;
#pragma unroll
            for (int ks = 0; ks < 4; ks++) {
                uint32_t a0 = sObs32[bp1 + offA[ks][0]];
                uint32_t a1 = sObs32[bp2 + offA[ks][0]];
                uint32_t a2 = sObs32[bp1 + offA[ks][1]];
                uint32_t a3 = sObs32[bp2 + offA[ks][1]];
#pragma unroll
                for (int nt = 0; nt < 2; nt++) {
                    int n = nt*8 + gid;
                    uint32_t b0 = sW1u[(ks*8 + tig)*16 + n];
                    uint32_t b1v = sW1u[(ks*8 + tig + 4)*16 + n];
                    MMA_TF32(accP[mt][nt], a0, a1, a2, a3, b0, b1v);
                }
            }
        }

        // bias+relu, zero invalid pixels, STS.64 k-pair interleaved
#pragma unroll
        for (int mt = 0; mt < 3; mt++) {
#pragma unroll
            for (int hp = 0; hp < 2; hp++) {
                int p = warp*48 + mt*16 + gid + hp*8;
                if (p < PPX) {
                    int pr = p / 34, pc = p - pr*34;
                    int hi = bh0 + pr - 1, wi = bw0 + pc - 1;
                    bool valid = (hi >= 0 && hi < NN && wi >= 0 && wi < NN);
                    uint32_t wlo = 0u, whi = 0u;
                    if (valid) {
                        int ch0 = 2*tig;           // nt = 0
                        int ch1 = 8 + 2*tig;       // nt = 1
                        wlo = packh2(fmaxf(accP[mt][0][hp*2]   + sb1[ch0],   0.0f),
                                     fmaxf(accP[mt][0][hp*2+1] + sb1[ch0+1], 0.0f));
                        whi = packh2(fmaxf(accP[mt][1][hp*2]   + sb1[ch1],   0.0f),
                                     fmaxf(accP[mt][1][hp*2+1] + sb1[ch1+1], 0.0f));
                    }
                    ((uint2*)sPu)[p*4 + tig] = make_uint2(wlo, whi);
                }
            }
        }
    }
    __syncthreads();

    // ---------- conv2 via fp16 MMA: one k16 chunk per tap, LDS.64 frags ------
    float acc[2][4][4];
#pragma unroll
    for (int mt = 0; mt < 2; mt++)
#pragma unroll
        for (int nt = 0; nt < 4; nt++)
#pragma unroll
            for (int q = 0; q < 4; q++) acc[mt][nt][q] = 0.0f;

    const uint2* sPu2 = (const uint2*)sPu;
    const uint2* sW2  = (const uint2*)sW2h;

#pragma unroll
    for (int th = 0; th < 3; th++) {
#pragma unroll
        for (int tw = 0; tw < 3; tw++) {
            int tap = th*3 + tw;
            uint2 bf[4];
#pragma unroll
            for (int nt = 0; nt < 4; nt++)
                bf[nt] = sW2[(tap*32 + nt*8 + gid)*4 + tig];
#pragma unroll
            for (int mt = 0; mt < 2; mt++) {
                int P1 = (warp + th)*34 + mt*16 + gid + tw;
                uint2 A0 = sPu2[P1*4 + tig];
                uint2 A1 = sPu2[(P1+8)*4 + tig];
#pragma unroll
                for (int nt = 0; nt < 4; nt++)
                    MMA_F16(acc[mt][nt], A0.x, A1.x, A0.y, A1.y,
                            bf[nt].x, bf[nt].y);
            }
        }
    }

    // ---------- register epilogue: quad-shuffle channel mean -----------------
    {
        float bv[4][2];
#pragma unroll
        for (int nt = 0; nt < 4; nt++) {
            bv[nt][0] = __ldg(b2 + nt*8 + 2*tig);
            bv[nt][1] = __ldg(b2 + nt*8 + 2*tig + 1);
        }
        int h = bh0 + warp;
#pragma unroll
        for (int mt = 0; mt < 2; mt++) {
#pragma unroll
            for (int rh = 0; rh < 2; rh++) {
                float y[8];
                float s = 0.0f;
#pragma unroll
                for (int nt = 0; nt < 4; nt++) {
                    float u0 = fmaxf(acc[mt][nt][rh*2]   + bv[nt][0], 0.0f);
                    float u1 = fmaxf(acc[mt][nt][rh*2+1] + bv[nt][1], 0.0f);
                    y[nt*2] = u0; y[nt*2+1] = u1;
                    s += u0 + u1;
                }
                s += __shfl_xor_sync(0xffffffff, s, 1);
                s += __shfl_xor_sync(0xffffffff, s, 2);
                int wq = bw0 + mt*16 + gid + rh*8;
                if (h < NN && wq < NN) {
                    if (tig == 0)
                        g_ahat[(size_t)b*NSQ + (size_t)wq*NN + h] =
                            s * (1.0f/32.0f) + (h == wq ? 1.0f : 0.0f);
                    if (h == wq) {
                        uint32_t* xp = g_x0h + ((size_t)b*NN + h)*16;
#pragma unroll
                        for (int nt = 0; nt < 4; nt++)
                            xp[nt*4 + tig] = packh2(y[nt*2], y[nt*2+1]);
                    }
                }
            }
        }
    }
}

// ------ merged: deg (blocks >= 147) + XW1^T fp16 MMA (blocks 0..146) ---------
__global__ void xwdeg_kernel() {
    if (blockIdx.x >= 147) {
        int bt = blockIdx.x - 147;
        const float* row = g_ahat + (size_t)bt * NN;
        int tid = threadIdx.x;
        float s = 0.0f;
        for (int i = tid; i < NN; i += 128) s += row[i];
#pragma unroll
        for (int o = 16; o > 0; o >>= 1) s += __shfl_xor_sync(0xffffffff, s, o);
        __shared__ float ws[4];
        if ((tid & 31) == 0) ws[tid >> 5] = s;
        __syncthreads();
        if (tid == 0) {
            float d = ws[0] + ws[1] + ws[2] + ws[3];
            g_dinv[bt] = d > 0.0f ? rsqrtf(d) : 0.0f;
        }
        return;
    }

    int lane = threadIdx.x & 31, warp = threadIdx.x >> 5;
    int gid = lane >> 2, tig = lane & 3;
    int m0 = blockIdx.x * 64 + warp * 16;

    float acc[8][4];
#pragma unroll
    for (int nt = 0; nt < 8; nt++)
#pragma unroll
        for (int q = 0; q < 4; q++) acc[nt][q] = 0.0f;

    int r0 = m0 + gid, r1 = r0 + 8;
#pragma unroll
    for (int ks = 0; ks < 2; ks++) {
        uint32_t a0 = g_x0h[(size_t)r0*16 + ks*8 + tig];
        uint32_t a1 = g_x0h[(size_t)r1*16 + ks*8 + tig];
        uint32_t a2 = g_x0h[(size_t)r0*16 + ks*8 + tig + 4];
        uint32_t a3 = g_x0h[(size_t)r1*16 + ks*8 + tig + 4];
#pragma unroll
        for (int nt = 0; nt < 8; nt++) {
            int n = nt*8 + gid;
            uint32_t b0 = g_wg1[n*16 + ks*8 + tig];
            uint32_t b1 = g_wg1[n*16 + ks*8 + tig + 4];
            MMA_F16(acc[nt], a0, a1, a2, a3, b0, b1);
        }
    }

    __half* dst = (__half*)g_xwTA;
    int b0i = r0 / NN, s0 = r0 - b0i*NN;
    int b1i = r1 / NN, s1 = r1 - b1i*NN;
#pragma unroll
    for (int nt = 0; nt < 8; nt++) {
        int col = nt*8 + 2*tig;
        dst[((size_t)b0i*128 + col    )*160 + s0] = __float2half(acc[nt][0]);
        dst[((size_t)b0i*128 + col + 1)*160 + s0] = __float2half(acc[nt][1]);
        dst[((size_t)b1i*128 + col    )*160 + s1] = __float2half(acc[nt][2]);
        dst[((size_t)b1i*128 + col + 1)*160 + s1] = __float2half(acc[nt][3]);
    }
}

// --- GCN layer: Y = relu(norm @ XW_in^T' + b); then XW_out^T = (Y @ Wn)^T ----
// FIRST: build normalized fp16 A-tile from ahat+dinv, cache it in g_normh.
// !FIRST: load the cached tile (uint4 copies, no cvt/mults).
// LAST: fuse mean-pool via masked shuffle reduce + atomicAdd into g_pool.
template<int FOUT, bool FIRST, bool LAST>
__global__ void __launch_bounds__(128)
gcn_kernel(const uint32_t* __restrict__ XWT_in,
           const float* __restrict__ bias,
           const uint32_t* __restrict__ Wn,
           uint32_t* __restrict__ XWT_out) {
    constexpr int NTW  = FOUT / 32;
    constexpr int SYW  = FOUT/2 + 4;
    __shared__ uint32_t sA[16 * 84];
    __shared__ float sds[160];
    __shared__ uint32_t sY[16 * SYW];

    int tid = threadIdx.x;
    int lane = tid & 31, warp = tid >> 5;
    int gid = lane >> 2, tig = lane & 3;
    int b = blockIdx.y, t0 = blockIdx.x * 16;
    uint32_t* tile = g_normh + ((size_t)b*10 + blockIdx.x) * 1344;

    if (FIRST) {
        for (int i = tid; i < 160; i += 128)
            sds[i] = (i < NN) ? g_dinv[b*NN + i] : 0.0f;
        __syncthreads();
        __half* sAh = (__half*)sA;
        const float* ab = g_ahat + (size_t)b * NSQ;
        for (int i = tid; i < 16*168; i += 128) {
            int r = i / 168, s = i - r*168;
            int t = t0 + r;
            float v = 0.0f;
            if (t < NN && s < NN) v = ab[(size_t)t*NN + s] * sds[t] * sds[s];
            sAh[r*168 + s] = __float2half(v);
        }
        __syncthreads();
        for (int i = tid; i < 1344; i += 128) tile[i] = sA[i];  // cache for L2/L3
    } else {
        for (int i = tid; i < 336; i += 128)
            ((uint4*)sA)[i] = __ldg((const uint4*)tile + i);
        __syncthreads();
    }

    float acc[NTW][4];
#pragma unroll
    for (int nt = 0; nt < NTW; nt++)
#pragma unroll
        for (int q = 0; q < 4; q++) acc[nt][q] = 0.0f;

    int wn0 = warp * (FOUT/4);
    const uint32_t* xwb = XWT_in + (size_t)b * 128 * 80;

#pragma unroll
    for (int ks = 0; ks < 10; ks++) {
        uint32_t a0 = sA[gid*84 + ks*8 + tig];
        uint32_t a1 = sA[(gid+8)*84 + ks*8 + tig];
        uint32_t a2 = sA[gid*84 + ks*8 + tig + 4];
        uint32_t a3 = sA[(gid+8)*84 + ks*8 + tig + 4];
#pragma unroll
        for (int nt = 0; nt < NTW; nt++) {
            int n = wn0 + nt*8 + gid;
            uint32_t b0 = __ldg(xwb + (size_t)n*80 + ks*8 + tig);
            uint32_t b1 = __ldg(xwb + (size_t)n*80 + ks*8 + tig + 4);
            MMA_F16(acc[nt], a0, a1, a2, a3, b0, b1);
        }
    }

    int r0 = t0 + gid, r1 = r0 + 8;
    float m0 = (r0 < NN) ? 1.0f : 0.0f;
    float m1 = (r1 < NN) ? 1.0f : 0.0f;
#pragma unroll
    for (int nt = 0; nt < NTW; nt++) {
        int col = wn0 + nt*8 + 2*tig;
        float bv0 = __ldg(bias + col), bv1 = __ldg(bias + col + 1);
        float y00 = fmaxf(acc[nt][0] + bv0, 0.0f);
        float y01 = fmaxf(acc[nt][1] + bv1, 0.0f);
        float y10 = fmaxf(acc[nt][2] + bv0, 0.0f);
        float y11 = fmaxf(acc[nt][3] + bv1, 0.0f);
        if (LAST) {
            float s0 = y00*m0 + y10*m1;
            float s1 = y01*m0 + y11*m1;
            s0 += __shfl_xor_sync(0xffffffffu, s0, 4);
            s0 += __shfl_xor_sync(0xffffffffu, s0, 8);
            s0 += __shfl_xor_sync(0xffffffffu, s0, 16);
            s1 += __shfl_xor_sync(0xffffffffu, s1, 4);
            s1 += __shfl_xor_sync(0xffffffffu, s1, 8);
            s1 += __shfl_xor_sync(0xffffffffu, s1, 16);
            if (gid == 0) {
                atomicAdd(&g_pool[b*128 + col],     s0);
                atomicAdd(&g_pool[b*128 + col + 1], s1);
            }
        } else {
            int wq = wn0/2 + nt*4 + tig;
            sY[gid*SYW + wq]     = packh2(y00, y01);
            sY[(gid+8)*SYW + wq] = packh2(y10, y11);
        }
    }

    if (!LAST) {
        __syncthreads();

        float acc2[4][4];
#pragma unroll
        for (int nt = 0; nt < 4; nt++)
#pragma unroll
            for (int q = 0; q < 4; q++) acc2[nt][q] = 0.0f;

        int wn2 = warp * 32;
#pragma unroll
        for (int ks = 0; ks < FOUT/16; ks++) {
            uint32_t a0 = sY[gid*SYW + ks*8 + tig];
            uint32_t a1 = sY[(gid+8)*SYW + ks*8 + tig];
            uint32_t a2 = sY[gid*SYW + ks*8 + tig + 4];
            uint32_t a3 = sY[(gid+8)*SYW + ks*8 + tig + 4];
#pragma unroll
            for (int nt = 0; nt < 4; nt++) {
                int n = wn2 + nt*8 + gid;
                uint32_t b0 = __ldg(Wn + n*(FOUT/2) + ks*8 + tig);
                uint32_t b1 = __ldg(Wn + n*(FOUT/2) + ks*8 + tig + 4);
                MMA_F16(acc2[nt], a0, a1, a2, a3, b0, b1);
            }
        }

        __half* dst = (__half*)XWT_out;
#pragma unroll
        for (int nt = 0; nt < 4; nt++) {
            int col = wn2 + nt*8 + 2*tig;
            if (r0 < NN) {
                dst[((size_t)b*128 + col    )*160 + r0] = __float2half(acc2[nt][0]);
                dst[((size_t)b*128 + col + 1)*160 + r0] = __float2half(acc2[nt][1]);
            }
            if (r1 < NN) {
                dst[((size_t)b*128 + col    )*160 + r1] = __float2half(acc2[nt][2]);
                dst[((size_t)b*128 + col + 1)*160 + r1] = __float2half(acc2[nt][3]);
            }
        }
    }
}

// ---------------- policy head from pooled sums -------------------------------
__global__ void head_kernel(const float* __restrict__ pw,
                            const float* __restrict__ pb,
                            float* __restrict__ out) {
    int b = blockIdx.x;
    int f = threadIdx.x;
    if (f < 5) {
        float a = __ldg(pb + f);
        const float sc = 1.0f / 147.0f;
        const float* pool = g_pool + b*128;
#pragma unroll 8
        for (int i = 0; i < 128; i++)
            a += pool[i] * sc * __ldg(pw + i*5 + f);
        out[b*5 + f] = a;
    }
}

// ---------------- launch -----------------------------------------------------
extern "C" void kernel_launch(void* const* d_in, const int* in_sizes, int n_in,
                              void* d_out, int out_size) {
    const float* obs      = (const float*)d_in[0];
    const float* conv1_w  = (const float*)d_in[1];
    const float* conv1_b  = (const float*)d_in[2];
    const float* conv2_w  = (const float*)d_in[3];
    const float* conv2_b  = (const float*)d_in[4];
    const float* gcn1_w   = (const float*)d_in[5];
    const float* gcn1_b   = (const float*)d_in[6];
    const float* gcn2_w   = (const float*)d_in[7];
    const float* gcn2_b   = (const float*)d_in[8];
    const float* gcn3_w   = (const float*)d_in[9];
    const float* gcn3_b   = (const float*)d_in[10];
    const float* policy_w = (const float*)d_in[11];
    const float* policy_b = (const float*)d_in[12];
    float* out = (float*)d_out;

    uint32_t *xwA, *xwB, *wg2, *wg3;
    cudaGetSymbolAddress((void**)&xwA, g_xwTA);
    cudaGetSymbolAddress((void**)&xwB, g_xwTB);
    cudaGetSymbolAddress((void**)&wg2, g_wg2);
    cudaGetSymbolAddress((void**)&wg3, g_wg3);

    prep_kernel<<<32, 256>>>(conv1_w, conv2_w, gcn1_w, gcn2_w, gcn3_w);
    conv_fused_kernel<<<dim3(5, 19, BB), 256>>>(obs, conv1_b, conv2_b);
    xwdeg_kernel<<<147 + BB*NN, 128>>>();

    gcn_kernel<64,  true,  false><<<dim3(10, BB), 128>>>(xwA, gcn1_b, wg2, xwB);
    gcn_kernel<128, false, false><<<dim3(10, BB), 128>>>(xwB, gcn2_b, wg3, xwA);
    gcn_kernel<128, false, true ><<<dim3(10, BB), 128>>>(xwA, gcn3_b, nullptr, nullptr);

    head_kernel<<<BB, 32>>>(policy_w, policy_b, out);
}

// round 17
// speedup vs baseline: 1.1012x; 1.0297x over previous
#include <cuda_runtime.h>
#include <cuda_fp16.h>
#include <cstdint>

#define BB 64
#define NN 147
#define NSQ (NN*NN)          // 21609

// ---------------- scratch (device globals; zero-initialized) -----------------
__device__ float g_ahat[(size_t)BB * NSQ];      // A_hat (unnormalized) [b][t][s]
__device__ float g_deg[BB * NN];                // degree sums (atomic)
__device__ float g_dinv[BB * NN];
__device__ uint32_t g_x0h[(size_t)BB * NN * 16];     // node feats fp16 [node][16 words]
__device__ uint32_t g_xwTA[(size_t)BB * 128 * 80];   // XW^T fp16 [b][f][160 s] ping
__device__ uint32_t g_xwTB[(size_t)BB * 128 * 80];   // pong (pads stay zero)
__device__ uint32_t g_normh[(size_t)BB * 10 * 1344]; // fp16 norm tiles [b][mt][16x84]
__device__ float g_pool[BB * 128];              // pooled sums (atomic)

__device__ uint32_t g_w2h[9*32*8];   // conv2 w fp16, k-pair interleaved
__device__ uint32_t g_w1t[32*16];    // conv1 w tf32: [k][o], k>=27 -> 0
__device__ uint32_t g_wg1[64*16];    // gcn1_w fp16 T: [n][q=k/2], K=32
__device__ uint32_t g_wg2[128*32];   // gcn2_w fp16 T: [n][q], K=64
__device__ uint32_t g_wg3[128*64];   // gcn3_w fp16 T: [n][q], K=128

__device__ __forceinline__ uint32_t f2tf32(float f) {
    uint32_t r;
    asm("cvt.rna.tf32.f32 %0, %1;" : "=r"(r) : "f"(f));
    return r;
}
__device__ __forceinline__ uint32_t packh2(float lo, float hi) {
    __half2 h = __floats2half2_rn(lo, hi);
    return *(uint32_t*)&h;
}

#define MMA_TF32(d, a0_, a1_, a2_, a3_, b0_, b1_)                              \
    asm volatile("mma.sync.aligned.m16n8k8.row.col.f32.tf32.tf32.f32 "         \
                 "{%0,%1,%2,%3}, {%4,%5,%6,%7}, {%8,%9}, {%0,%1,%2,%3};"       \
                 : "+f"((d)[0]), "+f"((d)[1]), "+f"((d)[2]), "+f"((d)[3])      \
                 : "r"(a0_), "r"(a1_), "r"(a2_), "r"(a3_), "r"(b0_), "r"(b1_))

#define MMA_F16(d, a0_, a1_, a2_, a3_, b0_, b1_)                               \
    asm volatile("mma.sync.aligned.m16n8k16.row.col.f32.f16.f16.f32 "          \
                 "{%0,%1,%2,%3}, {%4,%5,%6,%7}, {%8,%9}, {%0,%1,%2,%3};"       \
                 : "+f"((d)[0]), "+f"((d)[1]), "+f"((d)[2]), "+f"((d)[3])      \
                 : "r"(a0_), "r"(a1_), "r"(a2_), "r"(a3_), "r"(b0_), "r"(b1_))

// ---------------- one-time weight relayout/convert + scratch zero ------------
__global__ void prep_kernel(const float* __restrict__ w1,
                            const float* __restrict__ w2,
                            const float* __restrict__ wg1,
                            const float* __restrict__ wg2,
                            const float* __restrict__ wg3) {
    int i = blockIdx.x * 256 + threadIdx.x;
    if (i < 8192) g_pool[i] = 0.0f;
    if (i < BB*NN) g_deg[i] = 0.0f;
    if (i < 2304) {                      // conv2 -> fp16, k-pair interleaved
        int row = i >> 3, j = i & 7;
        int tap = row >> 5, o = row & 31;
        int ci0 = 2*(j >> 1) + (j & 1)*8;
        g_w2h[i] = packh2(w2[(o*16 + ci0)*9 + tap], w2[(o*16 + ci0 + 1)*9 + tap]);
    }
    if (i < 512) {                       // conv1 -> tf32, k>=27 zero
        int k = i >> 4, o = i & 15;
        uint32_t v = 0u;
        if (k < 27) {
            int tap = (k*11) >> 5, c = k - 3*tap;
            int kh = (tap*11) >> 5, kw = tap - 3*kh;
            v = f2tf32(w1[((o*3 + c)*3 + kh)*3 + kw]);   // OIHW
        }
        g_w1t[i] = v;
    }
    if (i < 1024) {
        int n = i >> 4, q = i & 15;
        g_wg1[i] = packh2(wg1[2*q*64 + n], wg1[(2*q + 1)*64 + n]);
    }
    if (i < 4096) {
        int n = i >> 5, q = i & 31;
        g_wg2[i] = packh2(wg2[2*q*128 + n], wg2[(2*q + 1)*128 + n]);
    }
    if (i < 8192) {
        int n = i >> 6, q = i & 63;
        g_wg3[i] = packh2(wg3[2*q*128 + n], wg3[(2*q + 1)*128 + n]);
    }
}

// ====== fused conv1(3->16, tf32 MMA) + conv2(16->32, fp16 MMA) + epilogue ====
// grid: (5, 19, B). block = 256 threads = 8x32 output tile (warp = 1 img row).
#define PST 8                             // patch pixel stride (words), k-interleaved
#define PPX 340                           // patch pixels: 10 rows x 34 cols
__global__ void __launch_bounds__(256)
conv_fused_kernel(const float* __restrict__ obs,
                  const float* __restrict__ b1,
                  const float* __restrict__ b2) {
    __shared__ uint32_t sW2h[9*32*8];     // 9.2 KB
    __shared__ uint32_t sPu[PPX*PST];     // 10.9 KB fp16 h1 patch (k-interleaved)
    __shared__ uint32_t sObs32[1408];     // 12x36x3 tf32 + zero pad
    __shared__ uint32_t sW1u[512];
    __shared__ float sb1[16];

    int tid = threadIdx.x;
    int lane = tid & 31, warp = tid >> 5;
    int gid = lane >> 2, tig = lane & 3;
    int b   = blockIdx.z;
    int bw0 = blockIdx.x * 32;
    int bh0 = blockIdx.y * 8;

    {   // stage weights: coalesced copies
        uint4* dst = (uint4*)sW2h;
        const uint4* src = (const uint4*)g_w2h;
        for (int i = tid; i < 576; i += 256) dst[i] = src[i];
        if (tid < 128) ((uint4*)sW1u)[tid] = ((const uint4*)g_w1t)[tid];
    }
    if (tid < 16) sb1[tid] = b1[tid];
    if (tid >= 144 && tid < 256) sObs32[1296 + tid - 144] = 0u;   // pad finite

    // obs halo patch (tf32): rows bh0-2..bh0+9, cols bw0-2..bw0+33
    for (int i = tid; i < 1296; i += 256) {
        int pr = i / 108, within = i - pr*108;
        int hi = bh0 + pr - 2;
        int wi = bw0 - 2 + within/3;
        float v = 0.0f;
        if (hi >= 0 && hi < NN && wi >= 0 && wi < NN)
            v = obs[(size_t)(b*NN + hi)*NN*3 + (bw0 - 2)*3 + within];
        sObs32[i] = f2tf32(v);
    }
    __syncthreads();

    // ---------- conv1 via tf32 MMA: A = 384 px x K32 im2col, B = w1 ---------
    {
        int offA[4][2];
#pragma unroll
        for (int ks = 0; ks < 4; ks++) {
#pragma unroll
            for (int hh = 0; hh < 2; hh++) {
                int k = ks*8 + tig + hh*4;
                int tap = (k*11) >> 5, c = k - 3*tap;
                int kh = (tap*11) >> 5, kw = tap - 3*kh;
                offA[ks][hh] = kh*108 + kw*3 + c;
            }
        }

        float accP[3][2][4];
#pragma unroll
        for (int mt = 0; mt < 3; mt++)
#pragma unroll
            for (int nt = 0; nt < 2; nt++)
#pragma unroll
                for (int q = 0; q < 4; q++) accP[mt][nt][q] = 0.0f;

#pragma unroll
        for (int mt = 0; mt < 3; mt++) {
            int p1 = warp*48 + mt*16 + gid;
            int p2 = p1 + 8;
            int p1c = min(p1, PPX-1), p2c = min(p2, PPX-1);
            int pr1 = p1c / 34, pr2 = p2c / 34;
            int bp1 = pr1*108 + (p1c - pr1*34)*3;
            int bp2 = pr2*108 + (p2c - pr2*34)*3;
#pragma unroll
            for (int ks = 0; ks < 4; ks++) {
                uint32_t a0 = sObs32[bp1 + offA[ks][0]];
                uint32_t a1 = sObs32[bp2 + offA[ks][0]];
                uint32_t a2 = sObs32[bp1 + offA[ks][1]];
                uint32_t a3 = sObs32[bp2 + offA[ks][1]];
#pragma unroll
                for (int nt = 0; nt < 2; nt++) {
                    int n = nt*8 + gid;
                    uint32_t b0 = sW1u[(ks*8 + tig)*16 + n];
                    uint32_t b1v = sW1u[(ks*8 + tig + 4)*16 + n];
                    MMA_TF32(accP[mt][nt], a0, a1, a2, a3, b0, b1v);
                }
            }
        }

        // bias+relu, zero invalid pixels, STS.64 k-pair interleaved
#pragma unroll
        for (int mt = 0; mt < 3; mt++) {
#pragma unroll
            for (int hp = 0; hp < 2; hp++) {
                int p = warp*48 + mt*16 + gid + hp*8;
                if (p < PPX) {
                    int pr = p / 34, pc = p - pr*34;
                    int hi = bh0 + pr - 1, wi = bw0 + pc - 1;
                    bool valid = (hi >= 0 && hi < NN && wi >= 0 && wi < NN);
                    uint32_t wlo = 0u, whi = 0u;
                    if (valid) {
                        int ch0 = 2*tig;           // nt = 0
                        int ch1 = 8 + 2*tig;       // nt = 1
                        wlo = packh2(fmaxf(accP[mt][0][hp*2]   + sb1[ch0],   0.0f),
                                     fmaxf(accP[mt][0][hp*2+1] + sb1[ch0+1], 0.0f));
                        whi = packh2(fmaxf(accP[mt][1][hp*2]   + sb1[ch1],   0.0f),
                                     fmaxf(accP[mt][1][hp*2+1] + sb1[ch1+1], 0.0f));
                    }
                    ((uint2*)sPu)[p*4 + tig] = make_uint2(wlo, whi);
                }
            }
        }
    }
    __syncthreads();

    // ---------- conv2 via fp16 MMA: one k16 chunk per tap, LDS.64 frags ------
    float acc[2][4][4];
#pragma unroll
    for (int mt = 0; mt < 2; mt++)
#pragma unroll
        for (int nt = 0; nt < 4; nt++)
#pragma unroll
            for (int q = 0; q < 4; q++) acc[mt][nt][q] = 0.0f;

    const uint2* sPu2 = (const uint2*)sPu;
    const uint2* sW2  = (const uint2*)sW2h;

#pragma unroll
    for (int th = 0; th < 3; th++) {
#pragma unroll
        for (int tw = 0; tw < 3; tw++) {
            int tap = th*3 + tw;
            uint2 bf[4];
#pragma unroll
            for (int nt = 0; nt < 4; nt++)
                bf[nt] = sW2[(tap*32 + nt*8 + gid)*4 + tig];
#pragma unroll
            for (int mt = 0; mt < 2; mt++) {
                int P1 = (warp + th)*34 + mt*16 + gid + tw;
                uint2 A0 = sPu2[P1*4 + tig];
                uint2 A1 = sPu2[(P1+8)*4 + tig];
#pragma unroll
                for (int nt = 0; nt < 4; nt++)
                    MMA_F16(acc[mt][nt], A0.x, A1.x, A0.y, A1.y,
                            bf[nt].x, bf[nt].y);
            }
        }
    }

    // ------ register epilogue: quad-shuffle channel mean + deg atomics -------
    {
        float bv[4][2];
#pragma unroll
        for (int nt = 0; nt < 4; nt++) {
            bv[nt][0] = __ldg(b2 + nt*8 + 2*tig);
            bv[nt][1] = __ldg(b2 + nt*8 + 2*tig + 1);
        }
        int h = bh0 + warp;
#pragma unroll
        for (int mt = 0; mt < 2; mt++) {
#pragma unroll
            for (int rh = 0; rh < 2; rh++) {
                float y[8];
                float s = 0.0f;
#pragma unroll
                for (int nt = 0; nt < 4; nt++) {
                    float u0 = fmaxf(acc[mt][nt][rh*2]   + bv[nt][0], 0.0f);
                    float u1 = fmaxf(acc[mt][nt][rh*2+1] + bv[nt][1], 0.0f);
                    y[nt*2] = u0; y[nt*2+1] = u1;
                    s += u0 + u1;
                }
                s += __shfl_xor_sync(0xffffffff, s, 1);
                s += __shfl_xor_sync(0xffffffff, s, 2);
                int wq = bw0 + mt*16 + gid + rh*8;
                if (h < NN && wq < NN) {
                    float aval = s * (1.0f/32.0f) + (h == wq ? 1.0f : 0.0f);
                    if (tig == 0) {
                        g_ahat[(size_t)b*NSQ + (size_t)wq*NN + h] = aval;
                        atomicAdd(&g_deg[b*NN + wq], aval);   // deg row-sum
                    }
                    if (h == wq) {
                        uint32_t* xp = g_x0h + ((size_t)b*NN + h)*16;
#pragma unroll
                        for (int nt = 0; nt < 4; nt++)
                            xp[nt*4 + tig] = packh2(y[nt*2], y[nt*2+1]);
                    }
                }
            }
        }
    }
}

// ------ merged: dinv (blocks >= 147, elementwise) + XW1^T fp16 MMA ----------
__global__ void xwdeg_kernel() {
    if (blockIdx.x >= 147) {
        int i = (blockIdx.x - 147)*128 + threadIdx.x;
        if (i < BB*NN) {
            float d = g_deg[i];
            g_dinv[i] = d > 0.0f ? rsqrtf(d) : 0.0f;
        }
        return;
    }

    int lane = threadIdx.x & 31, warp = threadIdx.x >> 5;
    int gid = lane >> 2, tig = lane & 3;
    int m0 = blockIdx.x * 64 + warp * 16;

    float acc[8][4];
#pragma unroll
    for (int nt = 0; nt < 8; nt++)
#pragma unroll
        for (int q = 0; q < 4; q++) acc[nt][q] = 0.0f;

    int r0 = m0 + gid, r1 = r0 + 8;
#pragma unroll
    for (int ks = 0; ks < 2; ks++) {
        uint32_t a0 = g_x0h[(size_t)r0*16 + ks*8 + tig];
        uint32_t a1 = g_x0h[(size_t)r1*16 + ks*8 + tig];
        uint32_t a2 = g_x0h[(size_t)r0*16 + ks*8 + tig + 4];
        uint32_t a3 = g_x0h[(size_t)r1*16 + ks*8 + tig + 4];
#pragma unroll
        for (int nt = 0; nt < 8; nt++) {
            int n = nt*8 + gid;
            uint32_t b0 = g_wg1[n*16 + ks*8 + tig];
            uint32_t b1 = g_wg1[n*16 + ks*8 + tig + 4];
            MMA_F16(acc[nt], a0, a1, a2, a3, b0, b1);
        }
    }

    __half* dst = (__half*)g_xwTA;
    int b0i = r0 / NN, s0 = r0 - b0i*NN;
    int b1i = r1 / NN, s1 = r1 - b1i*NN;
#pragma unroll
    for (int nt = 0; nt < 8; nt++) {
        int col = nt*8 + 2*tig;
        dst[((size_t)b0i*128 + col    )*160 + s0] = __float2half(acc[nt][0]);
        dst[((size_t)b0i*128 + col + 1)*160 + s0] = __float2half(acc[nt][1]);
        dst[((size_t)b1i*128 + col    )*160 + s1] = __float2half(acc[nt][2]);
        dst[((size_t)b1i*128 + col + 1)*160 + s1] = __float2half(acc[nt][3]);
    }
}

// --- GCN layer: Y = relu(norm @ XW_in^T' + b); then XW_out^T = (Y @ Wn)^T ----
// FIRST: build normalized fp16 A-tile from ahat+dinv, cache it in g_normh.
// !FIRST: load the cached tile (uint4 copies, no cvt/mults).
// LAST: fuse mean-pool via shuffle reduce + atomicAdd; n-split via blockIdx.z.
template<int FOUT, bool FIRST, bool LAST, int NSP>
__global__ void __launch_bounds__(128)
gcn_kernel(const uint32_t* __restrict__ XWT_in,
           const float* __restrict__ bias,
           const uint32_t* __restrict__ Wn,
           uint32_t* __restrict__ XWT_out) {
    constexpr int NTW  = FOUT / 32 / NSP;
    constexpr int SYW  = FOUT/2 + 4;
    __shared__ uint32_t sA[16 * 84];
    __shared__ float sds[160];
    __shared__ uint32_t sY[LAST ? 1 : 16 * SYW];

    int tid = threadIdx.x;
    int lane = tid & 31, warp = tid >> 5;
    int gid = lane >> 2, tig = lane & 3;
    int b = blockIdx.y, t0 = blockIdx.x * 16;
    uint32_t* tile = g_normh + ((size_t)b*10 + blockIdx.x) * 1344;

    if (FIRST) {
        for (int i = tid; i < 160; i += 128)
            sds[i] = (i < NN) ? g_dinv[b*NN + i] : 0.0f;
        __syncthreads();
        __half* sAh = (__half*)sA;
        const float* ab = g_ahat + (size_t)b * NSQ;
        for (int i = tid; i < 16*168; i += 128) {
            int r = i / 168, s = i - r*168;
            int t = t0 + r;
            float v = 0.0f;
            if (t < NN && s < NN) v = ab[(size_t)t*NN + s] * sds[t] * sds[s];
            sAh[r*168 + s] = __float2half(v);
        }
        __syncthreads();
        for (int i = tid; i < 1344; i += 128) tile[i] = sA[i];  // cache
    } else {
        for (int i = tid; i < 336; i += 128)
            ((uint4*)sA)[i] = __ldg((const uint4*)tile + i);
        __syncthreads();
    }

    float acc[NTW][4];
#pragma unroll
    for (int nt = 0; nt < NTW; nt++)
#pragma unroll
        for (int q = 0; q < 4; q++) acc[nt][q] = 0.0f;

    int wn0 = blockIdx.z * (FOUT/NSP) + warp * (FOUT/4/NSP);
    const uint32_t* xwb = XWT_in + (size_t)b * 128 * 80;

#pragma unroll
    for (int ks = 0; ks < 10; ks++) {
        uint32_t a0 = sA[gid*84 + ks*8 + tig];
        uint32_t a1 = sA[(gid+8)*84 + ks*8 + tig];
        uint32_t a2 = sA[gid*84 + ks*8 + tig + 4];
        uint32_t a3 = sA[(gid+8)*84 + ks*8 + tig + 4];
#pragma unroll
        for (int nt = 0; nt < NTW; nt++) {
            int n = wn0 + nt*8 + gid;
            uint32_t b0 = __ldg(xwb + (size_t)n*80 + ks*8 + tig);
            uint32_t b1 = __ldg(xwb + (size_t)n*80 + ks*8 + tig + 4);
            MMA_F16(acc[nt], a0, a1, a2, a3, b0, b1);
        }
    }

    int r0 = t0 + gid, r1 = r0 + 8;
    float m0 = (r0 < NN) ? 1.0f : 0.0f;
    float m1 = (r1 < NN) ? 1.0f : 0.0f;
#pragma unroll
    for (int nt = 0; nt < NTW; nt++) {
        int col = wn0 + nt*8 + 2*tig;
        float bv0 = __ldg(bias + col), bv1 = __ldg(bias + col + 1);
        float y00 = fmaxf(acc[nt][0] + bv0, 0.0f);
        float y01 = fmaxf(acc[nt][1] + bv1, 0.0f);
        float y10 = fmaxf(acc[nt][2] + bv0, 0.0f);
        float y11 = fmaxf(acc[nt][3] + bv1, 0.0f);
        if (LAST) {
            float s0 = y00*m0 + y10*m1;
            float s1 = y01*m0 + y11*m1;
            s0 += __shfl_xor_sync(0xffffffffu, s0, 4);
            s0 += __shfl_xor_sync(0xffffffffu, s0, 8);
            s0 += __shfl_xor_sync(0xffffffffu, s0, 16);
            s1 += __shfl_xor_sync(0xffffffffu, s1, 4);
            s1 += __shfl_xor_sync(0xffffffffu, s1, 8);
            s1 += __shfl_xor_sync(0xffffffffu, s1, 16);
            if (gid == 0) {
                atomicAdd(&g_pool[b*128 + col],     s0);
                atomicAdd(&g_pool[b*128 + col + 1], s1);
            }
        } else {
            int wq = wn0/2 + nt*4 + tig;
            sY[gid*SYW + wq]     = packh2(y00, y01);
            sY[(gid+8)*SYW + wq] = packh2(y10, y11);
        }
    }

    if (!LAST) {
        __syncthreads();

        float acc2[4][4];
#pragma unroll
        for (int nt = 0; nt < 4; nt++)
#pragma unroll
            for (int q = 0; q < 4; q++) acc2[nt][q] = 0.0f;

        int wn2 = warp * 32;
#pragma unroll
        for (int ks = 0; ks < FOUT/16; ks++) {
            uint32_t a0 = sY[gid*SYW + ks*8 + tig];
            uint32_t a1 = sY[(gid+8)*SYW + ks*8 + tig];
            uint32_t a2 = sY[gid*SYW + ks*8 + tig + 4];
            uint32_t a3 = sY[(gid+8)*SYW + ks*8 + tig + 4];
#pragma unroll
            for (int nt = 0; nt < 4; nt++) {
                int n = wn2 + nt*8 + gid;
                uint32_t b0 = __ldg(Wn + n*(FOUT/2) + ks*8 + tig);
                uint32_t b1 = __ldg(Wn + n*(FOUT/2) + ks*8 + tig + 4);
                MMA_F16(acc2[nt], a0, a1, a2, a3, b0, b1);
            }
        }

        __half* dst = (__half*)XWT_out;
#pragma unroll
        for (int nt = 0; nt < 4; nt++) {
            int col = wn2 + nt*8 + 2*tig;
            if (r0 < NN) {
                dst[((size_t)b*128 + col    )*160 + r0] = __float2half(acc2[nt][0]);
                dst[((size_t)b*128 + col + 1)*160 + r0] = __float2half(acc2[nt][1]);
            }
            if (r1 < NN) {
                dst[((size_t)b*128 + col    )*160 + r1] = __float2half(acc2[nt][2]);
                dst[((size_t)b*128 + col + 1)*160 + r1] = __float2half(acc2[nt][3]);
            }
        }
    }
}

// ---------------- policy head from pooled sums -------------------------------
__global__ void head_kernel(const float* __restrict__ pw,
                            const float* __restrict__ pb,
                            float* __restrict__ out) {
    int b = blockIdx.x;
    int f = threadIdx.x;
    if (f < 5) {
        float a = __ldg(pb + f);
        const float sc = 1.0f / 147.0f;
        const float* pool = g_pool + b*128;
#pragma unroll 8
        for (int i = 0; i < 128; i++)
            a += pool[i] * sc * __ldg(pw + i*5 + f);
        out[b*5 + f] = a;
    }
}

// ---------------- launch -----------------------------------------------------
extern "C" void kernel_launch(void* const* d_in, const int* in_sizes, int n_in,
                              void* d_out, int out_size) {
    const float* obs      = (const float*)d_in[0];
    const float* conv1_w  = (const float*)d_in[1];
    const float* conv1_b  = (const float*)d_in[2];
    const float* conv2_w  = (const float*)d_in[3];
    const float* conv2_b  = (const float*)d_in[4];
    const float* gcn1_w   = (const float*)d_in[5];
    const float* gcn1_b   = (const float*)d_in[6];
    const float* gcn2_w   = (const float*)d_in[7];
    const float* gcn2_b   = (const float*)d_in[8];
    const float* gcn3_w   = (const float*)d_in[9];
    const float* gcn3_b   = (const float*)d_in[10];
    const float* policy_w = (const float*)d_in[11];
    const float* policy_b = (const float*)d_in[12];
    float* out = (float*)d_out;

    uint32_t *xwA, *xwB, *wg2, *wg3;
    cudaGetSymbolAddress((void**)&xwA, g_xwTA);
    cudaGetSymbolAddress((void**)&xwB, g_xwTB);
    cudaGetSymbolAddress((void**)&wg2, g_wg2);
    cudaGetSymbolAddress((void**)&wg3, g_wg3);

    prep_kernel<<<37, 256>>>(conv1_w, conv2_w, gcn1_w, gcn2_w, gcn3_w);
    conv_fused_kernel<<<dim3(5, 19, BB), 256>>>(obs, conv1_b, conv2_b);
    xwdeg_kernel<<<147 + 74, 128>>>();

    gcn_kernel<64,  true,  false, 1><<<dim3(10, BB), 128>>>(xwA, gcn1_b, wg2, xwB);
    gcn_kernel<128, false, false, 1><<<dim3(10, BB), 128>>>(xwB, gcn2_b, wg3, xwA);
    gcn_kernel<128, false, true,  2><<<dim3(10, BB, 2), 128>>>(xwA, gcn3_b, nullptr, nullptr);

    head_kernel<<<BB, 32>>>(policy_w, policy_b, out);
}